// round 12
// baseline (speedup 1.0000x reference)
#include <cuda_runtime.h>
#include <cuda_bf16.h>
#include <math.h>
#include <stdint.h>

#define N_NODES 50000
#define IN_CH   128
#define E_EDGES 400000
#define E_TOT   (E_EDGES + N_NODES)   // with self loops
#define H1C     256                   // HEADS*HID
#define OUTC    64

// ---------------- scratch (device globals: allocation-free) ----------------
__device__ float g_H1  [(size_t)N_NODES * H1C];   // x @ W1 (fp32)
__device__ float g_Gcat[(size_t)N_NODES * 128];   // [h2 @ W_mu | h2 @ W_ls]
__device__ __nv_bfloat16 g_H2hi[(size_t)N_NODES * H1C];
__device__ __nv_bfloat16 g_H2lo[(size_t)N_NODES * H1C];
__device__ __nv_bfloat16 g_W1T_hi[256 * 128];   // [N=256 rows][K=128]
__device__ __nv_bfloat16 g_W1T_lo[256 * 128];
__device__ __nv_bfloat16 g_WcT_hi[128 * 256];   // [N=128 rows][K=256]
__device__ __nv_bfloat16 g_WcT_lo[128 * 256];
__device__ float g_A1src[N_NODES * 2];
__device__ float g_A1dst[N_NODES * 2];
__device__ float g_A2src[N_NODES * 2];
__device__ float g_A2dst[N_NODES * 2];
__device__ float g_att2src[128];   // [as_mu(64) | as_ls(64)]
__device__ float g_att2dst[128];   // [ad_mu(64) | ad_ls(64)]
__device__ float2 g_alpha[E_TOT];  // fallback scratch for deg>32 nodes
// CSR
__device__ int g_deg[N_NODES];
__device__ int g_ptr[N_NODES + 1];
__device__ int g_cursor[N_NODES];
__device__ int g_csrsrc[E_TOT];

// ---------------- low-level helpers ----------------
__device__ __forceinline__ uint32_t smem_u32(const void* p) {
    uint32_t a;
    asm("{ .reg .u64 t; cvta.to.shared.u64 t, %1; cvt.u32.u64 %0, t; }" : "=r"(a) : "l"(p));
    return a;
}
__device__ __forceinline__ void ldsm4(uint32_t* r, uint32_t addr) {
    asm volatile("ldmatrix.sync.aligned.m8n8.x4.shared.b16 {%0,%1,%2,%3}, [%4];"
                 : "=r"(r[0]), "=r"(r[1]), "=r"(r[2]), "=r"(r[3]) : "r"(addr));
}
__device__ __forceinline__ void mma_bf16(float* c, const uint32_t* a, uint32_t b0, uint32_t b1) {
    asm volatile("mma.sync.aligned.m16n8k16.row.col.f32.bf16.bf16.f32 "
                 "{%0,%1,%2,%3}, {%4,%5,%6,%7}, {%8,%9}, {%0,%1,%2,%3};"
                 : "+f"(c[0]), "+f"(c[1]), "+f"(c[2]), "+f"(c[3])
                 : "r"(a[0]), "r"(a[1]), "r"(a[2]), "r"(a[3]), "r"(b0), "r"(b1));
}
__device__ __forceinline__ float lrelu(float v) { return v > 0.f ? v : 0.2f * v; }
__device__ __forceinline__ void split2(float v, __nv_bfloat16& h, __nv_bfloat16& l) {
    h = __float2bfloat16(v);
    l = __float2bfloat16(v - __bfloat162float(h));
}
__device__ __forceinline__ float wmax(float v) {
#pragma unroll
    for (int o = 16; o; o >>= 1) v = fmaxf(v, __shfl_xor_sync(0xffffffffu, v, o));
    return v;
}
__device__ __forceinline__ float wsum(float v) {
#pragma unroll
    for (int o = 16; o; o >>= 1) v += __shfl_xor_sync(0xffffffffu, v, o);
    return v;
}

// ============================================================================
// Tensor-core GEMM (mma.sync bf16, hi/lo 3-product split) + fused attn logits.
// ============================================================================
template<int K, int NTOT, int CHEAD, bool AFP32>
__global__ __launch_bounds__(256, 2) void gemm_mma(
    const float* __restrict__ Afp,
    const __nv_bfloat16* __restrict__ Ahi, const __nv_bfloat16* __restrict__ Alo,
    const __nv_bfloat16* __restrict__ Bhi, const __nv_bfloat16* __restrict__ Blo,
    float* __restrict__ C,
    const float* __restrict__ attsrc, const float* __restrict__ attdst,
    float* __restrict__ asrc, float* __restrict__ adst, int M)
{
    __shared__ __align__(16) __nv_bfloat16 sAh[128 * 32];
    __shared__ __align__(16) __nv_bfloat16 sAl[128 * 32];
    __shared__ __align__(16) __nv_bfloat16 sBh[128 * 32];
    __shared__ __align__(16) __nv_bfloat16 sBl[128 * 32];
    __shared__ float sAtt[2][128];
    __shared__ float sRed[2][128][2];

    const int tid = threadIdx.x;
    const int lane = tid & 31;
    const int wid = tid >> 5;
    const int wr = wid & 3;
    const int wc = wid >> 2;
    const int m0 = blockIdx.x * 128;
    const int n0 = blockIdx.y * 128;

    for (int i = tid; i < 128; i += 256) {
        sAtt[0][i] = attsrc[n0 + i];
        sAtt[1][i] = attdst[n0 + i];
    }

    const uint32_t sAhB = smem_u32(sAh), sAlB = smem_u32(sAl);
    const uint32_t sBhB = smem_u32(sBh), sBlB = smem_u32(sBl);

    float acc[2][8][4];
#pragma unroll
    for (int i = 0; i < 2; i++)
#pragma unroll
        for (int j = 0; j < 8; j++)
#pragma unroll
            for (int l = 0; l < 4; l++) acc[i][j][l] = 0.f;

    const int a_row = wr * 32 + (lane & 7) + ((lane >> 3) & 1) * 8;
    const int a_chA = lane >> 4;
    const int b_row = wc * 64 + (lane & 7) + (lane >> 4) * 8;
    const int b_chB = (lane >> 3) & 1;

    for (int ks = 0; ks < K / 32; ks++) {
        if (AFP32) {
#pragma unroll
            for (int j = 0; j < 4; j++) {
                int idx = tid + j * 256;
                int row = idx >> 3, cg = idx & 7;
                int grA = m0 + row;
                float4 v = make_float4(0.f, 0.f, 0.f, 0.f);
                if (grA < M) v = *(const float4*)(Afp + (size_t)grA * K + ks * 32 + cg * 4);
                __nv_bfloat16 h0, h1, h2, h3, l0, l1, l2, l3;
                split2(v.x, h0, l0); split2(v.y, h1, l1);
                split2(v.z, h2, l2); split2(v.w, h3, l3);
                uint32_t soff = row * 64 + (((cg >> 1) ^ (row & 3)) << 4) + (cg & 1) * 8;
                __nv_bfloat162 hp0(h0, h1), hp1(h2, h3), lp0(l0, l1), lp1(l2, l3);
                *(uint2*)((char*)sAh + soff) = make_uint2(*(uint32_t*)&hp0, *(uint32_t*)&hp1);
                *(uint2*)((char*)sAl + soff) = make_uint2(*(uint32_t*)&lp0, *(uint32_t*)&lp1);
            }
        } else {
#pragma unroll
            for (int j = 0; j < 2; j++) {
                int idx = tid + j * 256;
                int row = idx >> 2, ch = idx & 3;
                uint32_t soff = row * 64 + ((ch ^ (row & 3)) << 4);
                int grA = m0 + row;
                size_t gofs = (size_t)grA * K + ks * 32 + ch * 8;
                uint4 va = make_uint4(0u, 0u, 0u, 0u), vb = va;
                if (grA < M) { va = *(const uint4*)(Ahi + gofs); vb = *(const uint4*)(Alo + gofs); }
                *(uint4*)((char*)sAh + soff) = va;
                *(uint4*)((char*)sAl + soff) = vb;
            }
        }
#pragma unroll
        for (int j = 0; j < 2; j++) {
            int idx = tid + j * 256;
            int row = idx >> 2, ch = idx & 3;
            uint32_t soff = row * 64 + ((ch ^ (row & 3)) << 4);
            size_t gofsB = (size_t)(n0 + row) * K + ks * 32 + ch * 8;
            *(uint4*)((char*)sBh + soff) = *(const uint4*)(Bhi + gofsB);
            *(uint4*)((char*)sBl + soff) = *(const uint4*)(Blo + gofsB);
        }
        __syncthreads();

#pragma unroll
        for (int k16 = 0; k16 < 2; k16++) {
            uint32_t ah[2][4], al[2][4];
#pragma unroll
            for (int mt = 0; mt < 2; mt++) {
                int row = a_row + mt * 16;
                int ch = k16 * 2 + a_chA;
                uint32_t off = row * 64 + ((ch ^ (row & 3)) << 4);
                ldsm4(ah[mt], sAhB + off);
                ldsm4(al[mt], sAlB + off);
            }
#pragma unroll
            for (int ntg = 0; ntg < 4; ntg++) {
                int row = b_row + ntg * 16;
                int ch = k16 * 2 + b_chB;
                uint32_t off = row * 64 + ((ch ^ (row & 3)) << 4);
                uint32_t bh[4], bl[4];
                ldsm4(bh, sBhB + off);
                ldsm4(bl, sBlB + off);
#pragma unroll
                for (int mt = 0; mt < 2; mt++) {
                    mma_bf16(acc[mt][ntg * 2 + 0], ah[mt], bh[0], bh[1]);
                    mma_bf16(acc[mt][ntg * 2 + 0], al[mt], bh[0], bh[1]);
                    mma_bf16(acc[mt][ntg * 2 + 0], ah[mt], bl[0], bl[1]);
                    mma_bf16(acc[mt][ntg * 2 + 1], ah[mt], bh[2], bh[3]);
                    mma_bf16(acc[mt][ntg * 2 + 1], al[mt], bh[2], bh[3]);
                    mma_bf16(acc[mt][ntg * 2 + 1], ah[mt], bl[2], bl[3]);
                }
            }
        }
        __syncthreads();
    }

    float pss[2][2] = {}, psd[2][2] = {};
#pragma unroll
    for (int mt = 0; mt < 2; mt++) {
        int rloc = wr * 32 + mt * 16 + (lane >> 2);
        int grow0 = m0 + rloc, grow1 = grow0 + 8;
#pragma unroll
        for (int nt = 0; nt < 8; nt++) {
            int cl = wc * 64 + nt * 8 + (lane & 3) * 2;
            float a0s = sAtt[0][cl], a1s = sAtt[0][cl + 1];
            float a0d = sAtt[1][cl], a1d = sAtt[1][cl + 1];
            float c0 = acc[mt][nt][0], c1 = acc[mt][nt][1];
            float c2 = acc[mt][nt][2], c3 = acc[mt][nt][3];
            pss[mt][0] += c0 * a0s + c1 * a1s;  psd[mt][0] += c0 * a0d + c1 * a1d;
            pss[mt][1] += c2 * a0s + c3 * a1s;  psd[mt][1] += c2 * a0d + c3 * a1d;
            if (grow0 < M) *(float2*)&C[(size_t)grow0 * NTOT + n0 + cl] = make_float2(c0, c1);
            if (grow1 < M) *(float2*)&C[(size_t)grow1 * NTOT + n0 + cl] = make_float2(c2, c3);
        }
    }
#pragma unroll
    for (int mt = 0; mt < 2; mt++)
#pragma unroll
        for (int h8 = 0; h8 < 2; h8++) {
            float vs = pss[mt][h8], vd = psd[mt][h8];
            vs += __shfl_xor_sync(0xffffffffu, vs, 1); vs += __shfl_xor_sync(0xffffffffu, vs, 2);
            vd += __shfl_xor_sync(0xffffffffu, vd, 1); vd += __shfl_xor_sync(0xffffffffu, vd, 2);
            if ((lane & 3) == 0) {
                int r = wr * 32 + mt * 16 + h8 * 8 + (lane >> 2);
                sRed[wc][r][0] = vs;
                sRed[wc][r][1] = vd;
            }
        }
    __syncthreads();
    for (int r = tid; r < 128; r += 256) {
        int node = m0 + r;
        if (node >= M) continue;
        if (CHEAD == 128) {
            int h = n0 >> 7;
            asrc[node * 2 + h] = sRed[0][r][0] + sRed[1][r][0];
            adst[node * 2 + h] = sRed[0][r][1] + sRed[1][r][1];
        } else {
            asrc[node * 2 + 0] = sRed[0][r][0];  adst[node * 2 + 0] = sRed[0][r][1];
            asrc[node * 2 + 1] = sRed[1][r][0];  adst[node * 2 + 1] = sRed[1][r][1];
        }
    }
}

// ---------------- prep ----------------
__global__ void prep_k(const float* __restrict__ W1,
                       const float* __restrict__ Wmu, const float* __restrict__ Wls,
                       const float* __restrict__ asmu, const float* __restrict__ asls,
                       const float* __restrict__ admu, const float* __restrict__ adls,
                       __nv_bfloat16* __restrict__ W1Th, __nv_bfloat16* __restrict__ W1Tl,
                       __nv_bfloat16* __restrict__ WcTh, __nv_bfloat16* __restrict__ WcTl,
                       float* __restrict__ a2s, float* __restrict__ a2d) {
    int i = blockIdx.x * blockDim.x + threadIdx.x;
    if (i < 256 * 128) {
        int n = i >> 7, k = i & 127;
        split2(W1[k * 256 + n], W1Th[i], W1Tl[i]);
    } else if (i < 2 * 256 * 128) {
        int j = i - 256 * 128;
        int n = j >> 8, k = j & 255;
        float w = (n < 64) ? Wmu[k * 64 + n] : Wls[k * 64 + (n - 64)];
        split2(w, WcTh[j], WcTl[j]);
    } else if (i < 2 * 256 * 128 + 128) {
        int j = i - 2 * 256 * 128;
        a2s[j] = (j < 64) ? asmu[j] : asls[j - 64];
    } else if (i < 2 * 256 * 128 + 256) {
        int j = i - 2 * 256 * 128 - 128;
        a2d[j] = (j < 64) ? admu[j] : adls[j - 64];
    }
}

// ---------------- CSR build ----------------
__global__ void csr_count_k(const int* __restrict__ ei, int* __restrict__ deg) {
    int e = blockIdx.x * blockDim.x + threadIdx.x;
    if (e >= E_TOT) return;
    int d = (e < E_EDGES) ? ei[E_EDGES + e] : e - E_EDGES;
    atomicAdd(&deg[d], 1);
}

// single-block exclusive scan of deg -> ptr (+cursor copy)
__global__ void scan_onepass_k(const int* __restrict__ deg, int* __restrict__ ptr,
                               int* __restrict__ cursor) {
    __shared__ int sh[1024];
    const int t = threadIdx.x;
    const int per = (N_NODES + 1023) / 1024;   // 49
    int base = t * per;
    int sum = 0;
    for (int i = 0; i < per; i++) {
        int idx = base + i;
        if (idx < N_NODES) sum += deg[idx];
    }
    sh[t] = sum;
    __syncthreads();
    int v = sum;
#pragma unroll
    for (int off = 1; off < 1024; off <<= 1) {
        int u = (t >= off) ? sh[t - off] : 0;
        __syncthreads();
        sh[t] += u;
        __syncthreads();
    }
    int run = sh[t] - v;   // exclusive prefix
    for (int i = 0; i < per; i++) {
        int idx = base + i;
        if (idx < N_NODES) {
            ptr[idx] = run;
            cursor[idx] = run;
            run += deg[idx];
        }
    }
    if (t == 0) ptr[N_NODES] = E_TOT;
}

__global__ void csr_fill_k(const int* __restrict__ ei, int* __restrict__ cursor,
                           int* __restrict__ csrsrc) {
    int e = blockIdx.x * blockDim.x + threadIdx.x;
    if (e >= E_TOT) return;
    int s, d;
    if (e < E_EDGES) { s = ei[e]; d = ei[E_EDGES + e]; }
    else             { s = d = e - E_EDGES; }
    int pos = atomicAdd(&cursor[d], 1);
    csrsrc[pos] = s;
}

// ============================================================================
// Warp softmax over incoming edges (fast path deg<=32; fallback via g_alpha).
// ============================================================================
__device__ __forceinline__ void warp_softmax(
    const float* __restrict__ As, float2 ad,
    const int* __restrict__ csrsrc, float2* __restrict__ alpha,
    int p0, int deg, int lane,
    int& sreg, float& a0, float& a1, float& inv0, float& inv1)
{
    if (deg <= 32) {
        sreg = 0;
        float l0 = -1e30f, l1 = -1e30f;
        if (lane < deg) {
            sreg = csrsrc[p0 + lane];
            float2 as = *(const float2*)&As[sreg * 2];
            l0 = lrelu(as.x + ad.x);
            l1 = lrelu(as.y + ad.y);
        }
        float m0 = wmax(l0), m1 = wmax(l1);
        float e0 = (lane < deg) ? __expf(l0 - m0) : 0.f;
        float e1 = (lane < deg) ? __expf(l1 - m1) : 0.f;
        inv0 = 1.f / (wsum(e0) + 1e-16f);
        inv1 = 1.f / (wsum(e1) + 1e-16f);
        a0 = e0 * inv0;
        a1 = e1 * inv1;
    } else {
        float m0 = -1e30f, m1 = -1e30f;
        for (int e = lane; e < deg; e += 32) {
            int s = csrsrc[p0 + e];
            float2 as = *(const float2*)&As[s * 2];
            m0 = fmaxf(m0, lrelu(as.x + ad.x));
            m1 = fmaxf(m1, lrelu(as.y + ad.y));
        }
        m0 = wmax(m0); m1 = wmax(m1);
        float d0 = 0.f, d1 = 0.f;
        for (int e = lane; e < deg; e += 32) {
            int s = csrsrc[p0 + e];
            float2 as = *(const float2*)&As[s * 2];
            float e0 = __expf(lrelu(as.x + ad.x) - m0);
            float e1 = __expf(lrelu(as.y + ad.y) - m1);
            alpha[p0 + e] = make_float2(e0, e1);
            d0 += e0; d1 += e1;
        }
        inv0 = 1.f / (wsum(d0) + 1e-16f);
        inv1 = 1.f / (wsum(d1) + 1e-16f);
        sreg = 0; a0 = 0.f; a1 = 0.f;
    }
}

// ============================================================================
// Layer-1 fused softmax + aggregate (+bias, ELU, bf16 split). One warp/node.
// ============================================================================
__global__ __launch_bounds__(256) void agg1_k(
    const float* __restrict__ H1, const float* __restrict__ A1s, const float* __restrict__ A1d,
    const int* __restrict__ ptr, const int* __restrict__ csrsrc,
    float2* __restrict__ alpha, const float* __restrict__ b1,
    __nv_bfloat16* __restrict__ h2h, __nv_bfloat16* __restrict__ h2l)
{
    int node = (blockIdx.x * 256 + threadIdx.x) >> 5;
    if (node >= N_NODES) return;
    int lane = threadIdx.x & 31;
    int p0 = ptr[node], deg = ptr[node + 1] - p0;
    float2 ad = *(const float2*)&A1d[node * 2];

    int sreg; float a0, a1, inv0, inv1;
    warp_softmax(A1s, ad, csrsrc, alpha, p0, deg, lane, sreg, a0, a1, inv0, inv1);

    float c0[4] = {}, c1[4] = {};
    if (deg <= 32) {
#pragma unroll 8
        for (int j = 0; j < deg; j++) {
            int s = __shfl_sync(0xffffffffu, sreg, j);
            float al0 = __shfl_sync(0xffffffffu, a0, j);
            float al1 = __shfl_sync(0xffffffffu, a1, j);
            const float4* row = (const float4*)(H1 + (size_t)s * H1C);
            float4 r0 = row[lane], r1 = row[32 + lane];
            c0[0] += al0 * r0.x; c0[1] += al0 * r0.y; c0[2] += al0 * r0.z; c0[3] += al0 * r0.w;
            c1[0] += al1 * r1.x; c1[1] += al1 * r1.y; c1[2] += al1 * r1.z; c1[3] += al1 * r1.w;
        }
    } else {
        for (int base = 0; base < deg; base += 32) {
            int cnt = min(32, deg - base);
            int idx = p0 + base + lane;
            int sr = 0; float b0 = 0.f, b1v = 0.f;
            if (base + lane < deg) {
                sr = csrsrc[idx];
                float2 av = alpha[idx];
                b0 = av.x * inv0; b1v = av.y * inv1;
            }
            for (int j = 0; j < cnt; j++) {
                int s = __shfl_sync(0xffffffffu, sr, j);
                float al0 = __shfl_sync(0xffffffffu, b0, j);
                float al1 = __shfl_sync(0xffffffffu, b1v, j);
                const float4* row = (const float4*)(H1 + (size_t)s * H1C);
                float4 r0 = row[lane], r1 = row[32 + lane];
                c0[0] += al0 * r0.x; c0[1] += al0 * r0.y; c0[2] += al0 * r0.z; c0[3] += al0 * r0.w;
                c1[0] += al1 * r1.x; c1[1] += al1 * r1.y; c1[2] += al1 * r1.z; c1[3] += al1 * r1.w;
            }
        }
    }

    int ch0 = lane * 4;
    float4 bb0 = *(const float4*)&b1[ch0];
    float4 bb1 = *(const float4*)&b1[128 + ch0];
    float v[8] = {c0[0] + bb0.x, c0[1] + bb0.y, c0[2] + bb0.z, c0[3] + bb0.w,
                  c1[0] + bb1.x, c1[1] + bb1.y, c1[2] + bb1.z, c1[3] + bb1.w};
    __nv_bfloat16 hh[8], ll[8];
#pragma unroll
    for (int i = 0; i < 8; i++) {
        float e = v[i] > 0.f ? v[i] : expm1f(v[i]);
        split2(e, hh[i], ll[i]);
    }
    size_t o0 = (size_t)node * H1C + ch0;
    size_t o1 = o0 + 128;
    *(__nv_bfloat162*)&h2h[o0]     = __nv_bfloat162(hh[0], hh[1]);
    *(__nv_bfloat162*)&h2h[o0 + 2] = __nv_bfloat162(hh[2], hh[3]);
    *(__nv_bfloat162*)&h2h[o1]     = __nv_bfloat162(hh[4], hh[5]);
    *(__nv_bfloat162*)&h2h[o1 + 2] = __nv_bfloat162(hh[6], hh[7]);
    *(__nv_bfloat162*)&h2l[o0]     = __nv_bfloat162(ll[0], ll[1]);
    *(__nv_bfloat162*)&h2l[o0 + 2] = __nv_bfloat162(ll[2], ll[3]);
    *(__nv_bfloat162*)&h2l[o1]     = __nv_bfloat162(ll[4], ll[5]);
    *(__nv_bfloat162*)&h2l[o1 + 2] = __nv_bfloat162(ll[6], ll[7]);
}

// ============================================================================
// Layer-2 fused softmax + aggregate (+bias). One warp/node.
// ============================================================================
__global__ __launch_bounds__(256) void agg2_k(
    const float* __restrict__ G, const float* __restrict__ A2s, const float* __restrict__ A2d,
    const int* __restrict__ ptr, const int* __restrict__ csrsrc,
    float2* __restrict__ alpha,
    const float* __restrict__ bmu, const float* __restrict__ bls,
    float* __restrict__ out)
{
    int node = (blockIdx.x * 256 + threadIdx.x) >> 5;
    if (node >= N_NODES) return;
    int lane = threadIdx.x & 31;
    int p0 = ptr[node], deg = ptr[node + 1] - p0;
    float2 ad = *(const float2*)&A2d[node * 2];

    int sreg; float a0, a1, inv0, inv1;
    warp_softmax(A2s, ad, csrsrc, alpha, p0, deg, lane, sreg, a0, a1, inv0, inv1);

    int h = lane >> 4;
    float cx = 0.f, cy = 0.f, cz = 0.f, cw = 0.f;
    if (deg <= 32) {
#pragma unroll 8
        for (int j = 0; j < deg; j++) {
            int s = __shfl_sync(0xffffffffu, sreg, j);
            float al0 = __shfl_sync(0xffffffffu, a0, j);
            float al1 = __shfl_sync(0xffffffffu, a1, j);
            float al = h ? al1 : al0;
            float4 r = ((const float4*)(G + (size_t)s * 128))[lane];
            cx += al * r.x; cy += al * r.y; cz += al * r.z; cw += al * r.w;
        }
    } else {
        for (int base = 0; base < deg; base += 32) {
            int cnt = min(32, deg - base);
            int idx = p0 + base + lane;
            int sr = 0; float b0 = 0.f, b1v = 0.f;
            if (base + lane < deg) {
                sr = csrsrc[idx];
                float2 av = alpha[idx];
                b0 = av.x * inv0; b1v = av.y * inv1;
            }
            for (int j = 0; j < cnt; j++) {
                int s = __shfl_sync(0xffffffffu, sr, j);
                float al0 = __shfl_sync(0xffffffffu, b0, j);
                float al1 = __shfl_sync(0xffffffffu, b1v, j);
                float al = h ? al1 : al0;
                float4 r = ((const float4*)(G + (size_t)s * 128))[lane];
                cx += al * r.x; cy += al * r.y; cz += al * r.z; cw += al * r.w;
            }
        }
    }
    int cl = (lane & 15) * 4;
    float4 bb = h ? *(const float4*)&bls[cl] : *(const float4*)&bmu[cl];
    float* dp = out + (size_t)h * N_NODES * OUTC + (size_t)node * OUTC + cl;
    *(float4*)dp = make_float4(cx + bb.x, cy + bb.y, cz + bb.z, cw + bb.w);
}

// ---------------- launch ----------------
extern "C" void kernel_launch(void* const* d_in, const int* in_sizes, int n_in,
                              void* d_out, int out_size) {
    const float* x        = (const float*)d_in[0];
    const int*   ei       = (const int*)  d_in[1];
    const float* W1       = (const float*)d_in[2];
    const float* att_src1 = (const float*)d_in[3];
    const float* att_dst1 = (const float*)d_in[4];
    const float* b1       = (const float*)d_in[5];
    const float* W_mu     = (const float*)d_in[6];
    const float* as_mu    = (const float*)d_in[7];
    const float* ad_mu    = (const float*)d_in[8];
    const float* b_mu     = (const float*)d_in[9];
    const float* W_ls     = (const float*)d_in[10];
    const float* as_ls    = (const float*)d_in[11];
    const float* ad_ls    = (const float*)d_in[12];
    const float* b_ls     = (const float*)d_in[13];
    float* out = (float*)d_out;

    float *H1, *Gcat, *A1s, *A1d, *A2s, *A2d, *a2s, *a2d;
    float2* alpha;
    __nv_bfloat16 *H2hi, *H2lo, *W1Th, *W1Tl, *WcTh, *WcTl;
    int *deg, *ptr, *cursor, *csrsrc;
    cudaGetSymbolAddress((void**)&H1,   g_H1);
    cudaGetSymbolAddress((void**)&Gcat, g_Gcat);
    cudaGetSymbolAddress((void**)&A1s,  g_A1src);
    cudaGetSymbolAddress((void**)&A1d,  g_A1dst);
    cudaGetSymbolAddress((void**)&A2s,  g_A2src);
    cudaGetSymbolAddress((void**)&A2d,  g_A2dst);
    cudaGetSymbolAddress((void**)&a2s,  g_att2src);
    cudaGetSymbolAddress((void**)&a2d,  g_att2dst);
    cudaGetSymbolAddress((void**)&alpha, g_alpha);
    cudaGetSymbolAddress((void**)&H2hi, g_H2hi);
    cudaGetSymbolAddress((void**)&H2lo, g_H2lo);
    cudaGetSymbolAddress((void**)&W1Th, g_W1T_hi);
    cudaGetSymbolAddress((void**)&W1Tl, g_W1T_lo);
    cudaGetSymbolAddress((void**)&WcTh, g_WcT_hi);
    cudaGetSymbolAddress((void**)&WcTl, g_WcT_lo);
    cudaGetSymbolAddress((void**)&deg,    g_deg);
    cudaGetSymbolAddress((void**)&ptr,    g_ptr);
    cudaGetSymbolAddress((void**)&cursor, g_cursor);
    cudaGetSymbolAddress((void**)&csrsrc, g_csrsrc);

    // ---- CSR build ----
    cudaMemsetAsync(deg, 0, N_NODES * sizeof(int));
    csr_count_k<<<(E_TOT + 255) / 256, 256>>>(ei, deg);
    scan_onepass_k<<<1, 1024>>>(deg, ptr, cursor);
    csr_fill_k<<<(E_TOT + 255) / 256, 256>>>(ei, cursor, csrsrc);

    // ---- data prep ----
    prep_k<<<(2 * 256 * 128 + 256 + 255) / 256, 256>>>(W1, W_mu, W_ls, as_mu, as_ls, ad_mu, ad_ls,
                                                       W1Th, W1Tl, WcTh, WcTl, a2s, a2d);

    const int gx = (N_NODES + 127) / 128;
    const int aggBlocks = (N_NODES * 32 + 255) / 256;

    // ---- layer 1 ----
    gemm_mma<128, 256, 128, true><<<dim3(gx, 2), 256>>>(
        x, nullptr, nullptr, W1Th, W1Tl, H1, att_src1, att_dst1, A1s, A1d, N_NODES);
    agg1_k<<<aggBlocks, 256>>>(H1, A1s, A1d, ptr, csrsrc, alpha, b1, H2hi, H2lo);

    // ---- layer 2 ----
    gemm_mma<256, 128, 64, false><<<dim3(gx, 1), 256>>>(
        nullptr, H2hi, H2lo, WcTh, WcTl, Gcat, a2s, a2d, A2s, A2d, N_NODES);
    agg2_k<<<aggBlocks, 256>>>(Gcat, A2s, A2d, ptr, csrsrc, alpha, b_mu, b_ls, out);
}

// round 15
// speedup vs baseline: 2.0240x; 2.0240x over previous
#include <cuda_runtime.h>
#include <cuda_bf16.h>
#include <math.h>
#include <stdint.h>

#define N_NODES 50000
#define IN_CH   128
#define E_EDGES 400000
#define E_TOT   (E_EDGES + N_NODES)   // with self loops
#define HID     128                   // per-head channels of conv1
#define H1C     256                   // HEADS*HID
#define OUTC    64
#define NBLK    ((N_NODES + 255) / 256)   // scan blocks

// ---------------- scratch (device globals: allocation-free) ----------------
__device__ float g_H1  [(size_t)N_NODES * H1C];   // x @ W1 (fp32)
__device__ float g_Gcat[(size_t)N_NODES * 128];   // [h2 @ W_mu | h2 @ W_ls]
__device__ __nv_bfloat16 g_H2hi[(size_t)N_NODES * H1C];
__device__ __nv_bfloat16 g_H2lo[(size_t)N_NODES * H1C];
__device__ __nv_bfloat16 g_W1T_hi[256 * 128];   // [N=256 rows][K=128]
__device__ __nv_bfloat16 g_W1T_lo[256 * 128];
__device__ __nv_bfloat16 g_WcT_hi[128 * 256];   // [N=128 rows][K=256]
__device__ __nv_bfloat16 g_WcT_lo[128 * 256];
__device__ float g_A1src[N_NODES * 2];
__device__ float g_A1dst[N_NODES * 2];
__device__ float g_A2src[N_NODES * 2];
__device__ float g_A2dst[N_NODES * 2];
__device__ float g_att2src[128];   // [as_mu(64) | as_ls(64)]
__device__ float g_att2dst[128];   // [ad_mu(64) | ad_ls(64)]
__device__ float2 g_alpha[E_TOT];  // fallback scratch for deg>32 nodes
// CSR
__device__ int g_deg[N_NODES];
__device__ int g_ptr[N_NODES + 1];
__device__ int g_cursor[N_NODES];
__device__ int g_csrsrc[E_TOT];
__device__ int g_blockSum[NBLK];
__device__ int g_blockOff[NBLK];

// ---------------- low-level helpers ----------------
__device__ __forceinline__ uint32_t smem_u32(const void* p) {
    uint32_t a;
    asm("{ .reg .u64 t; cvta.to.shared.u64 t, %1; cvt.u32.u64 %0, t; }" : "=r"(a) : "l"(p));
    return a;
}
__device__ __forceinline__ void ldsm4(uint32_t* r, uint32_t addr) {
    asm volatile("ldmatrix.sync.aligned.m8n8.x4.shared.b16 {%0,%1,%2,%3}, [%4];"
                 : "=r"(r[0]), "=r"(r[1]), "=r"(r[2]), "=r"(r[3]) : "r"(addr));
}
__device__ __forceinline__ void mma_bf16(float* c, const uint32_t* a, uint32_t b0, uint32_t b1) {
    asm volatile("mma.sync.aligned.m16n8k16.row.col.f32.bf16.bf16.f32 "
                 "{%0,%1,%2,%3}, {%4,%5,%6,%7}, {%8,%9}, {%0,%1,%2,%3};"
                 : "+f"(c[0]), "+f"(c[1]), "+f"(c[2]), "+f"(c[3])
                 : "r"(a[0]), "r"(a[1]), "r"(a[2]), "r"(a[3]), "r"(b0), "r"(b1));
}
__device__ __forceinline__ float lrelu(float v) { return v > 0.f ? v : 0.2f * v; }
__device__ __forceinline__ void split2(float v, __nv_bfloat16& h, __nv_bfloat16& l) {
    h = __float2bfloat16(v);
    l = __float2bfloat16(v - __bfloat162float(h));
}
__device__ __forceinline__ float wmax(float v) {
#pragma unroll
    for (int o = 16; o; o >>= 1) v = fmaxf(v, __shfl_xor_sync(0xffffffffu, v, o));
    return v;
}
__device__ __forceinline__ float wsum(float v) {
#pragma unroll
    for (int o = 16; o; o >>= 1) v += __shfl_xor_sync(0xffffffffu, v, o);
    return v;
}

// ============================================================================
// Tensor-core GEMM (mma.sync bf16, hi/lo 3-product split) + fused attn logits.
// ============================================================================
template<int K, int NTOT, int CHEAD, bool AFP32>
__global__ __launch_bounds__(256, 2) void gemm_mma(
    const float* __restrict__ Afp,
    const __nv_bfloat16* __restrict__ Ahi, const __nv_bfloat16* __restrict__ Alo,
    const __nv_bfloat16* __restrict__ Bhi, const __nv_bfloat16* __restrict__ Blo,
    float* __restrict__ C,
    const float* __restrict__ attsrc, const float* __restrict__ attdst,
    float* __restrict__ asrc, float* __restrict__ adst, int M)
{
    __shared__ __align__(16) __nv_bfloat16 sAh[128 * 32];
    __shared__ __align__(16) __nv_bfloat16 sAl[128 * 32];
    __shared__ __align__(16) __nv_bfloat16 sBh[128 * 32];
    __shared__ __align__(16) __nv_bfloat16 sBl[128 * 32];
    __shared__ float sAtt[2][128];
    __shared__ float sRed[2][128][2];

    const int tid = threadIdx.x;
    const int lane = tid & 31;
    const int wid = tid >> 5;
    const int wr = wid & 3;
    const int wc = wid >> 2;
    const int m0 = blockIdx.x * 128;
    const int n0 = blockIdx.y * 128;

    for (int i = tid; i < 128; i += 256) {
        sAtt[0][i] = attsrc[n0 + i];
        sAtt[1][i] = attdst[n0 + i];
    }

    const uint32_t sAhB = smem_u32(sAh), sAlB = smem_u32(sAl);
    const uint32_t sBhB = smem_u32(sBh), sBlB = smem_u32(sBl);

    float acc[2][8][4];
#pragma unroll
    for (int i = 0; i < 2; i++)
#pragma unroll
        for (int j = 0; j < 8; j++)
#pragma unroll
            for (int l = 0; l < 4; l++) acc[i][j][l] = 0.f;

    const int a_row = wr * 32 + (lane & 7) + ((lane >> 3) & 1) * 8;
    const int a_chA = lane >> 4;
    const int b_row = wc * 64 + (lane & 7) + (lane >> 4) * 8;
    const int b_chB = (lane >> 3) & 1;

    for (int ks = 0; ks < K / 32; ks++) {
        if (AFP32) {
#pragma unroll
            for (int j = 0; j < 4; j++) {
                int idx = tid + j * 256;
                int row = idx >> 3, cg = idx & 7;
                int grA = m0 + row;
                float4 v = make_float4(0.f, 0.f, 0.f, 0.f);
                if (grA < M) v = *(const float4*)(Afp + (size_t)grA * K + ks * 32 + cg * 4);
                __nv_bfloat16 h0, h1, h2, h3, l0, l1, l2, l3;
                split2(v.x, h0, l0); split2(v.y, h1, l1);
                split2(v.z, h2, l2); split2(v.w, h3, l3);
                uint32_t soff = row * 64 + (((cg >> 1) ^ (row & 3)) << 4) + (cg & 1) * 8;
                __nv_bfloat162 hp0(h0, h1), hp1(h2, h3), lp0(l0, l1), lp1(l2, l3);
                *(uint2*)((char*)sAh + soff) = make_uint2(*(uint32_t*)&hp0, *(uint32_t*)&hp1);
                *(uint2*)((char*)sAl + soff) = make_uint2(*(uint32_t*)&lp0, *(uint32_t*)&lp1);
            }
        } else {
#pragma unroll
            for (int j = 0; j < 2; j++) {
                int idx = tid + j * 256;
                int row = idx >> 2, ch = idx & 3;
                uint32_t soff = row * 64 + ((ch ^ (row & 3)) << 4);
                int grA = m0 + row;
                size_t gofs = (size_t)grA * K + ks * 32 + ch * 8;
                uint4 va = make_uint4(0u, 0u, 0u, 0u), vb = va;
                if (grA < M) { va = *(const uint4*)(Ahi + gofs); vb = *(const uint4*)(Alo + gofs); }
                *(uint4*)((char*)sAh + soff) = va;
                *(uint4*)((char*)sAl + soff) = vb;
            }
        }
#pragma unroll
        for (int j = 0; j < 2; j++) {
            int idx = tid + j * 256;
            int row = idx >> 2, ch = idx & 3;
            uint32_t soff = row * 64 + ((ch ^ (row & 3)) << 4);
            size_t gofsB = (size_t)(n0 + row) * K + ks * 32 + ch * 8;
            *(uint4*)((char*)sBh + soff) = *(const uint4*)(Bhi + gofsB);
            *(uint4*)((char*)sBl + soff) = *(const uint4*)(Blo + gofsB);
        }
        __syncthreads();

#pragma unroll
        for (int k16 = 0; k16 < 2; k16++) {
            uint32_t ah[2][4], al[2][4];
#pragma unroll
            for (int mt = 0; mt < 2; mt++) {
                int row = a_row + mt * 16;
                int ch = k16 * 2 + a_chA;
                uint32_t off = row * 64 + ((ch ^ (row & 3)) << 4);
                ldsm4(ah[mt], sAhB + off);
                ldsm4(al[mt], sAlB + off);
            }
#pragma unroll
            for (int ntg = 0; ntg < 4; ntg++) {
                int row = b_row + ntg * 16;
                int ch = k16 * 2 + b_chB;
                uint32_t off = row * 64 + ((ch ^ (row & 3)) << 4);
                uint32_t bh[4], bl[4];
                ldsm4(bh, sBhB + off);
                ldsm4(bl, sBlB + off);
#pragma unroll
                for (int mt = 0; mt < 2; mt++) {
                    mma_bf16(acc[mt][ntg * 2 + 0], ah[mt], bh[0], bh[1]);
                    mma_bf16(acc[mt][ntg * 2 + 0], al[mt], bh[0], bh[1]);
                    mma_bf16(acc[mt][ntg * 2 + 0], ah[mt], bl[0], bl[1]);
                    mma_bf16(acc[mt][ntg * 2 + 1], ah[mt], bh[2], bh[3]);
                    mma_bf16(acc[mt][ntg * 2 + 1], al[mt], bh[2], bh[3]);
                    mma_bf16(acc[mt][ntg * 2 + 1], ah[mt], bl[2], bl[3]);
                }
            }
        }
        __syncthreads();
    }

    float pss[2][2] = {}, psd[2][2] = {};
#pragma unroll
    for (int mt = 0; mt < 2; mt++) {
        int rloc = wr * 32 + mt * 16 + (lane >> 2);
        int grow0 = m0 + rloc, grow1 = grow0 + 8;
#pragma unroll
        for (int nt = 0; nt < 8; nt++) {
            int cl = wc * 64 + nt * 8 + (lane & 3) * 2;
            float a0s = sAtt[0][cl], a1s = sAtt[0][cl + 1];
            float a0d = sAtt[1][cl], a1d = sAtt[1][cl + 1];
            float c0 = acc[mt][nt][0], c1 = acc[mt][nt][1];
            float c2 = acc[mt][nt][2], c3 = acc[mt][nt][3];
            pss[mt][0] += c0 * a0s + c1 * a1s;  psd[mt][0] += c0 * a0d + c1 * a1d;
            pss[mt][1] += c2 * a0s + c3 * a1s;  psd[mt][1] += c2 * a0d + c3 * a1d;
            if (grow0 < M) *(float2*)&C[(size_t)grow0 * NTOT + n0 + cl] = make_float2(c0, c1);
            if (grow1 < M) *(float2*)&C[(size_t)grow1 * NTOT + n0 + cl] = make_float2(c2, c3);
        }
    }
#pragma unroll
    for (int mt = 0; mt < 2; mt++)
#pragma unroll
        for (int h8 = 0; h8 < 2; h8++) {
            float vs = pss[mt][h8], vd = psd[mt][h8];
            vs += __shfl_xor_sync(0xffffffffu, vs, 1); vs += __shfl_xor_sync(0xffffffffu, vs, 2);
            vd += __shfl_xor_sync(0xffffffffu, vd, 1); vd += __shfl_xor_sync(0xffffffffu, vd, 2);
            if ((lane & 3) == 0) {
                int r = wr * 32 + mt * 16 + h8 * 8 + (lane >> 2);
                sRed[wc][r][0] = vs;
                sRed[wc][r][1] = vd;
            }
        }
    __syncthreads();
    for (int r = tid; r < 128; r += 256) {
        int node = m0 + r;
        if (node >= M) continue;
        if (CHEAD == 128) {
            int h = n0 >> 7;
            asrc[node * 2 + h] = sRed[0][r][0] + sRed[1][r][0];
            adst[node * 2 + h] = sRed[0][r][1] + sRed[1][r][1];
        } else {
            asrc[node * 2 + 0] = sRed[0][r][0];  adst[node * 2 + 0] = sRed[0][r][1];
            asrc[node * 2 + 1] = sRed[1][r][0];  adst[node * 2 + 1] = sRed[1][r][1];
        }
    }
}

// ---------------- prep ----------------
__global__ void prep_k(const float* __restrict__ W1,
                       const float* __restrict__ Wmu, const float* __restrict__ Wls,
                       const float* __restrict__ asmu, const float* __restrict__ asls,
                       const float* __restrict__ admu, const float* __restrict__ adls,
                       __nv_bfloat16* __restrict__ W1Th, __nv_bfloat16* __restrict__ W1Tl,
                       __nv_bfloat16* __restrict__ WcTh, __nv_bfloat16* __restrict__ WcTl,
                       float* __restrict__ a2s, float* __restrict__ a2d) {
    int i = blockIdx.x * blockDim.x + threadIdx.x;
    if (i < 256 * 128) {
        int n = i >> 7, k = i & 127;
        split2(W1[k * 256 + n], W1Th[i], W1Tl[i]);
    } else if (i < 2 * 256 * 128) {
        int j = i - 256 * 128;
        int n = j >> 8, k = j & 255;
        float w = (n < 64) ? Wmu[k * 64 + n] : Wls[k * 64 + (n - 64)];
        split2(w, WcTh[j], WcTl[j]);
    } else if (i < 2 * 256 * 128 + 128) {
        int j = i - 2 * 256 * 128;
        a2s[j] = (j < 64) ? asmu[j] : asls[j - 64];
    } else if (i < 2 * 256 * 128 + 256) {
        int j = i - 2 * 256 * 128 - 128;
        a2d[j] = (j < 64) ? admu[j] : adls[j - 64];
    }
}

// ---------------- CSR build ----------------
__global__ void csr_count_k(const int* __restrict__ ei, int* __restrict__ deg) {
    int e = blockIdx.x * blockDim.x + threadIdx.x;
    if (e >= E_TOT) return;
    int d = (e < E_EDGES) ? ei[E_EDGES + e] : e - E_EDGES;
    atomicAdd(&deg[d], 1);
}

__global__ void scanA_k(const int* __restrict__ deg, int* __restrict__ ptr,
                        int* __restrict__ blockSum) {
    __shared__ int sh[256];
    int i = blockIdx.x * 256 + threadIdx.x;
    int v = (i < N_NODES) ? deg[i] : 0;
    sh[threadIdx.x] = v;
    __syncthreads();
#pragma unroll
    for (int off = 1; off < 256; off <<= 1) {
        int t = (threadIdx.x >= off) ? sh[threadIdx.x - off] : 0;
        __syncthreads();
        sh[threadIdx.x] += t;
        __syncthreads();
    }
    if (i < N_NODES) ptr[i] = sh[threadIdx.x] - v;
    if (threadIdx.x == 255) blockSum[blockIdx.x] = sh[255];
}

__global__ void scanB_k(const int* __restrict__ blockSum, int* __restrict__ blockOff) {
    __shared__ int sh[256];
    int v = (threadIdx.x < NBLK) ? blockSum[threadIdx.x] : 0;
    sh[threadIdx.x] = v;
    __syncthreads();
#pragma unroll
    for (int off = 1; off < 256; off <<= 1) {
        int t = (threadIdx.x >= off) ? sh[threadIdx.x - off] : 0;
        __syncthreads();
        sh[threadIdx.x] += t;
        __syncthreads();
    }
    if (threadIdx.x < NBLK) blockOff[threadIdx.x] = sh[threadIdx.x] - v;
}

__global__ void scanC_k(int* __restrict__ ptr, const int* __restrict__ blockOff,
                        int* __restrict__ cursor) {
    int i = blockIdx.x * blockDim.x + threadIdx.x;
    if (i < N_NODES) {
        int v = ptr[i] + blockOff[i >> 8];
        ptr[i] = v;
        cursor[i] = v;
    }
    if (i == 0) ptr[N_NODES] = E_TOT;
}

__global__ void csr_fill_k(const int* __restrict__ ei, int* __restrict__ cursor,
                           int* __restrict__ csrsrc) {
    int e = blockIdx.x * blockDim.x + threadIdx.x;
    if (e >= E_TOT) return;
    int s, d;
    if (e < E_EDGES) { s = ei[e]; d = ei[E_EDGES + e]; }
    else             { s = d = e - E_EDGES; }
    int pos = atomicAdd(&cursor[d], 1);
    csrsrc[pos] = s;
}

// ============================================================================
// Warp softmax over incoming edges (fast path deg<=32; fallback via g_alpha).
// ============================================================================
__device__ __forceinline__ void warp_softmax(
    const float* __restrict__ As, float2 ad,
    const int* __restrict__ csrsrc, float2* __restrict__ alpha,
    int p0, int deg, int lane,
    int& sreg, float& a0, float& a1, float& inv0, float& inv1)
{
    if (deg <= 32) {
        sreg = 0;
        float l0 = -1e30f, l1 = -1e30f;
        if (lane < deg) {
            sreg = csrsrc[p0 + lane];
            float2 as = *(const float2*)&As[sreg * 2];
            l0 = lrelu(as.x + ad.x);
            l1 = lrelu(as.y + ad.y);
        }
        float m0 = wmax(l0), m1 = wmax(l1);
        float e0 = (lane < deg) ? __expf(l0 - m0) : 0.f;
        float e1 = (lane < deg) ? __expf(l1 - m1) : 0.f;
        inv0 = 1.f / (wsum(e0) + 1e-16f);
        inv1 = 1.f / (wsum(e1) + 1e-16f);
        a0 = e0 * inv0;
        a1 = e1 * inv1;
    } else {
        float m0 = -1e30f, m1 = -1e30f;
        for (int e = lane; e < deg; e += 32) {
            int s = csrsrc[p0 + e];
            float2 as = *(const float2*)&As[s * 2];
            m0 = fmaxf(m0, lrelu(as.x + ad.x));
            m1 = fmaxf(m1, lrelu(as.y + ad.y));
        }
        m0 = wmax(m0); m1 = wmax(m1);
        float d0 = 0.f, d1 = 0.f;
        for (int e = lane; e < deg; e += 32) {
            int s = csrsrc[p0 + e];
            float2 as = *(const float2*)&As[s * 2];
            float e0 = __expf(lrelu(as.x + ad.x) - m0);
            float e1 = __expf(lrelu(as.y + ad.y) - m1);
            alpha[p0 + e] = make_float2(e0, e1);
            d0 += e0; d1 += e1;
        }
        inv0 = 1.f / (wsum(d0) + 1e-16f);
        inv1 = 1.f / (wsum(d1) + 1e-16f);
        sreg = 0; a0 = 0.f; a1 = 0.f;
    }
}

// ============================================================================
// Layer-1 fused softmax + aggregate (+bias, ELU, bf16 split). One warp/node.
// ============================================================================
__global__ __launch_bounds__(256) void agg1_k(
    const float* __restrict__ H1, const float* __restrict__ A1s, const float* __restrict__ A1d,
    const int* __restrict__ ptr, const int* __restrict__ csrsrc,
    float2* __restrict__ alpha, const float* __restrict__ b1,
    __nv_bfloat16* __restrict__ h2h, __nv_bfloat16* __restrict__ h2l)
{
    int node = (blockIdx.x * 256 + threadIdx.x) >> 5;
    if (node >= N_NODES) return;
    int lane = threadIdx.x & 31;
    int p0 = ptr[node], deg = ptr[node + 1] - p0;
    float2 ad = *(const float2*)&A1d[node * 2];

    int sreg; float a0, a1, inv0, inv1;
    warp_softmax(A1s, ad, csrsrc, alpha, p0, deg, lane, sreg, a0, a1, inv0, inv1);

    float c0[4] = {}, c1[4] = {};
    if (deg <= 32) {
#pragma unroll 4
        for (int j = 0; j < deg; j++) {
            int s = __shfl_sync(0xffffffffu, sreg, j);
            float al0 = __shfl_sync(0xffffffffu, a0, j);
            float al1 = __shfl_sync(0xffffffffu, a1, j);
            const float4* row = (const float4*)(H1 + (size_t)s * H1C);
            float4 r0 = row[lane], r1 = row[32 + lane];
            c0[0] += al0 * r0.x; c0[1] += al0 * r0.y; c0[2] += al0 * r0.z; c0[3] += al0 * r0.w;
            c1[0] += al1 * r1.x; c1[1] += al1 * r1.y; c1[2] += al1 * r1.z; c1[3] += al1 * r1.w;
        }
    } else {
        for (int base = 0; base < deg; base += 32) {
            int cnt = min(32, deg - base);
            int idx = p0 + base + lane;
            int sr = 0; float b0 = 0.f, b1v = 0.f;
            if (base + lane < deg) {
                sr = csrsrc[idx];
                float2 av = alpha[idx];
                b0 = av.x * inv0; b1v = av.y * inv1;
            }
            for (int j = 0; j < cnt; j++) {
                int s = __shfl_sync(0xffffffffu, sr, j);
                float al0 = __shfl_sync(0xffffffffu, b0, j);
                float al1 = __shfl_sync(0xffffffffu, b1v, j);
                const float4* row = (const float4*)(H1 + (size_t)s * H1C);
                float4 r0 = row[lane], r1 = row[32 + lane];
                c0[0] += al0 * r0.x; c0[1] += al0 * r0.y; c0[2] += al0 * r0.z; c0[3] += al0 * r0.w;
                c1[0] += al1 * r1.x; c1[1] += al1 * r1.y; c1[2] += al1 * r1.z; c1[3] += al1 * r1.w;
            }
        }
    }

    int ch0 = lane * 4;
    float4 bb0 = *(const float4*)&b1[ch0];
    float4 bb1 = *(const float4*)&b1[128 + ch0];
    float v[8] = {c0[0] + bb0.x, c0[1] + bb0.y, c0[2] + bb0.z, c0[3] + bb0.w,
                  c1[0] + bb1.x, c1[1] + bb1.y, c1[2] + bb1.z, c1[3] + bb1.w};
    __nv_bfloat16 hh[8], ll[8];
#pragma unroll
    for (int i = 0; i < 8; i++) {
        float e = v[i] > 0.f ? v[i] : expm1f(v[i]);
        split2(e, hh[i], ll[i]);
    }
    size_t o0 = (size_t)node * H1C + ch0;
    size_t o1 = o0 + 128;
    *(__nv_bfloat162*)&h2h[o0]     = __nv_bfloat162(hh[0], hh[1]);
    *(__nv_bfloat162*)&h2h[o0 + 2] = __nv_bfloat162(hh[2], hh[3]);
    *(__nv_bfloat162*)&h2h[o1]     = __nv_bfloat162(hh[4], hh[5]);
    *(__nv_bfloat162*)&h2h[o1 + 2] = __nv_bfloat162(hh[6], hh[7]);
    *(__nv_bfloat162*)&h2l[o0]     = __nv_bfloat162(ll[0], ll[1]);
    *(__nv_bfloat162*)&h2l[o0 + 2] = __nv_bfloat162(ll[2], ll[3]);
    *(__nv_bfloat162*)&h2l[o1]     = __nv_bfloat162(ll[4], ll[5]);
    *(__nv_bfloat162*)&h2l[o1 + 2] = __nv_bfloat162(ll[6], ll[7]);
}

// ============================================================================
// Layer-2 fused softmax + aggregate (+bias). One warp/node.
// ============================================================================
__global__ __launch_bounds__(256) void agg2_k(
    const float* __restrict__ G, const float* __restrict__ A2s, const float* __restrict__ A2d,
    const int* __restrict__ ptr, const int* __restrict__ csrsrc,
    float2* __restrict__ alpha,
    const float* __restrict__ bmu, const float* __restrict__ bls,
    float* __restrict__ out)
{
    int node = (blockIdx.x * 256 + threadIdx.x) >> 5;
    if (node >= N_NODES) return;
    int lane = threadIdx.x & 31;
    int p0 = ptr[node], deg = ptr[node + 1] - p0;
    float2 ad = *(const float2*)&A2d[node * 2];

    int sreg; float a0, a1, inv0, inv1;
    warp_softmax(A2s, ad, csrsrc, alpha, p0, deg, lane, sreg, a0, a1, inv0, inv1);

    int h = lane >> 4;
    float cx = 0.f, cy = 0.f, cz = 0.f, cw = 0.f;
    if (deg <= 32) {
#pragma unroll 4
        for (int j = 0; j < deg; j++) {
            int s = __shfl_sync(0xffffffffu, sreg, j);
            float al0 = __shfl_sync(0xffffffffu, a0, j);
            float al1 = __shfl_sync(0xffffffffu, a1, j);
            float al = h ? al1 : al0;
            float4 r = ((const float4*)(G + (size_t)s * 128))[lane];
            cx += al * r.x; cy += al * r.y; cz += al * r.z; cw += al * r.w;
        }
    } else {
        for (int base = 0; base < deg; base += 32) {
            int cnt = min(32, deg - base);
            int idx = p0 + base + lane;
            int sr = 0; float b0 = 0.f, b1v = 0.f;
            if (base + lane < deg) {
                sr = csrsrc[idx];
                float2 av = alpha[idx];
                b0 = av.x * inv0; b1v = av.y * inv1;
            }
            for (int j = 0; j < cnt; j++) {
                int s = __shfl_sync(0xffffffffu, sr, j);
                float al0 = __shfl_sync(0xffffffffu, b0, j);
                float al1 = __shfl_sync(0xffffffffu, b1v, j);
                float al = h ? al1 : al0;
                float4 r = ((const float4*)(G + (size_t)s * 128))[lane];
                cx += al * r.x; cy += al * r.y; cz += al * r.z; cw += al * r.w;
            }
        }
    }
    int cl = (lane & 15) * 4;
    float4 bb = h ? *(const float4*)&bls[cl] : *(const float4*)&bmu[cl];
    float* dp = out + (size_t)h * N_NODES * OUTC + (size_t)node * OUTC + cl;
    *(float4*)dp = make_float4(cx + bb.x, cy + bb.y, cz + bb.z, cw + bb.w);
}

// ---------------- launch ----------------
extern "C" void kernel_launch(void* const* d_in, const int* in_sizes, int n_in,
                              void* d_out, int out_size) {
    const float* x        = (const float*)d_in[0];
    const int*   ei       = (const int*)  d_in[1];
    const float* W1       = (const float*)d_in[2];
    const float* att_src1 = (const float*)d_in[3];
    const float* att_dst1 = (const float*)d_in[4];
    const float* b1       = (const float*)d_in[5];
    const float* W_mu     = (const float*)d_in[6];
    const float* as_mu    = (const float*)d_in[7];
    const float* ad_mu    = (const float*)d_in[8];
    const float* b_mu     = (const float*)d_in[9];
    const float* W_ls     = (const float*)d_in[10];
    const float* as_ls    = (const float*)d_in[11];
    const float* ad_ls    = (const float*)d_in[12];
    const float* b_ls     = (const float*)d_in[13];
    float* out = (float*)d_out;

    float *H1, *Gcat, *A1s, *A1d, *A2s, *A2d, *a2s, *a2d;
    float2* alpha;
    __nv_bfloat16 *H2hi, *H2lo, *W1Th, *W1Tl, *WcTh, *WcTl;
    int *deg, *ptr, *cursor, *csrsrc, *blockSum, *blockOff;
    cudaGetSymbolAddress((void**)&H1,   g_H1);
    cudaGetSymbolAddress((void**)&Gcat, g_Gcat);
    cudaGetSymbolAddress((void**)&A1s,  g_A1src);
    cudaGetSymbolAddress((void**)&A1d,  g_A1dst);
    cudaGetSymbolAddress((void**)&A2s,  g_A2src);
    cudaGetSymbolAddress((void**)&A2d,  g_A2dst);
    cudaGetSymbolAddress((void**)&a2s,  g_att2src);
    cudaGetSymbolAddress((void**)&a2d,  g_att2dst);
    cudaGetSymbolAddress((void**)&alpha, g_alpha);
    cudaGetSymbolAddress((void**)&H2hi, g_H2hi);
    cudaGetSymbolAddress((void**)&H2lo, g_H2lo);
    cudaGetSymbolAddress((void**)&W1Th, g_W1T_hi);
    cudaGetSymbolAddress((void**)&W1Tl, g_W1T_lo);
    cudaGetSymbolAddress((void**)&WcTh, g_WcT_hi);
    cudaGetSymbolAddress((void**)&WcTl, g_WcT_lo);
    cudaGetSymbolAddress((void**)&deg,    g_deg);
    cudaGetSymbolAddress((void**)&ptr,    g_ptr);
    cudaGetSymbolAddress((void**)&cursor, g_cursor);
    cudaGetSymbolAddress((void**)&csrsrc, g_csrsrc);
    cudaGetSymbolAddress((void**)&blockSum, g_blockSum);
    cudaGetSymbolAddress((void**)&blockOff, g_blockOff);

    // ---- CSR build ----
    cudaMemsetAsync(deg, 0, N_NODES * sizeof(int));
    csr_count_k<<<(E_TOT + 255) / 256, 256>>>(ei, deg);
    scanA_k<<<NBLK, 256>>>(deg, ptr, blockSum);
    scanB_k<<<1, 256>>>(blockSum, blockOff);
    scanC_k<<<NBLK, 256>>>(ptr, blockOff, cursor);
    csr_fill_k<<<(E_TOT + 255) / 256, 256>>>(ei, cursor, csrsrc);

    // ---- data prep ----
    prep_k<<<(2 * 256 * 128 + 256 + 255) / 256, 256>>>(W1, W_mu, W_ls, as_mu, as_ls, ad_mu, ad_ls,
                                                       W1Th, W1Tl, WcTh, WcTl, a2s, a2d);

    const int gx = (N_NODES + 127) / 128;
    const int aggBlocks = (N_NODES * 32 + 255) / 256;

    // ---- layer 1 ----
    gemm_mma<128, 256, 128, true><<<dim3(gx, 2), 256>>>(
        x, nullptr, nullptr, W1Th, W1Tl, H1, att_src1, att_dst1, A1s, A1d, N_NODES);
    agg1_k<<<aggBlocks, 256>>>(H1, A1s, A1d, ptr, csrsrc, alpha, b1, H2hi, H2lo);

    // ---- layer 2 ----
    gemm_mma<256, 128, 64, false><<<dim3(gx, 1), 256>>>(
        nullptr, H2hi, H2lo, WcTh, WcTl, Gcat, a2s, a2d, A2s, A2d, N_NODES);
    agg2_k<<<aggBlocks, 256>>>(Gcat, A2s, A2d, ptr, csrsrc, alpha, b_mu, b_ls, out);
}